// round 9
// baseline (speedup 1.0000x reference)
#include <cuda_runtime.h>
#include <math.h>
#include <stdint.h>

#define DZ 64
#define DC 32
#define TILE 64
#define THREADS 128
#define ZS_STRIDE 68          // floats/row: conflict-free frag loads (4g+a distinct)
#define BS_STRIDE 65          // padded beta row: conflict-free bs[c*65+d] reads
#define TH_FAST 2.5e-4f       // tf32 -> exact-fp32 re-decide trigger (proven R7/R8)
#define TH_MED  4e-6f         // fp32 -> exact-double re-decide trigger (proven R6-R8)
#define GRID 592              // 148 SMs x 4 blocks: persistent

__device__ __forceinline__ uint32_t to_tf32(float f) {
    uint32_t r;
    asm("cvt.rna.tf32.f32 %0, %1;" : "=r"(r) : "f"(f));
    return r;
}

#define MMA_TF32(C, a0, a1, a2, a3, b0, b1)                                   \
    asm("mma.sync.aligned.m16n8k8.row.col.f32.tf32.tf32.f32 "                 \
        "{%0,%1,%2,%3}, {%4,%5,%6,%7}, {%8,%9}, {%0,%1,%2,%3};"               \
        : "+f"(C[0]), "+f"(C[1]), "+f"(C[2]), "+f"(C[3])                      \
        : "r"(a0), "r"(a1), "r"(a2), "r"(a3), "r"(b0), "r"(b1))

// Cold path: exact reference emulation (proven R3/R6/R7/R8).
//   double accumulate -> fp32 -> exp -> sequential norm -> IEEE divide
//   -> first-index argmax over probs.
__device__ __noinline__ int decide_exact(const float* __restrict__ zrow,
                                         const float* __restrict__ bs,
                                         int lane)
{
    int bi = 0;
    if (lane == 0) {
        float e[DC];
#pragma unroll 1
        for (int c = 0; c < DC - 1; c++) {
            double sd = 0.0;
#pragma unroll 1
            for (int d = 0; d < DZ; d++)
                sd += (double)zrow[d] * (double)bs[c * BS_STRIDE + d];
            float lf = (float)sd;
            e[c] = (float)exp((double)lf);
        }
        e[DC - 1] = 1.0f;
        float se = e[0];
#pragma unroll 1
        for (int c = 1; c < DC - 1; c++) se += e[c];
        const float norm = 1.0f + se;
        float pb = -1.0f;
#pragma unroll 1
        for (int c = 0; c < DC; c++) {
            float p = __fdiv_rn(e[c], norm);
            if (p > pb) { pb = p; bi = c; }   // strict > = first index
        }
    }
    return __shfl_sync(0xffffffffu, bi, 0);
}

__global__ __launch_bounds__(THREADS, 4)
void dec_cat_kernel(const float* __restrict__ Z,
                    const float* __restrict__ beta,
                    float* __restrict__ out,
                    int T)
{
    __shared__ float zs[2][TILE * ZS_STRIDE];    // double-buffered z tiles (34 KB)
    __shared__ float bs[(DC - 1) * BS_STRIDE];   // exact fp32 beta, padded (8 KB)

    const int tid  = threadIdx.x;
    const int lane = tid & 31;
    const int w    = tid >> 5;
    const int a    = lane & 3;    // threadID in group
    const int g    = lane >> 2;   // groupID (quad)

    // ---- one-time setup (amortized over ~53 tiles) ----
    for (int i = tid; i < (DC - 1) * DZ; i += THREADS)
        bs[(i >> 6) * BS_STRIDE + (i & 63)] = beta[i];

    // B fragments (tf32) in registers: b0=(k=a, n=g), b1=(k=a+4, n=g)
    uint32_t bf[8][4][2];
#pragma unroll
    for (int kt = 0; kt < 8; kt++)
#pragma unroll
        for (int nt = 0; nt < 4; nt++) {
            int n  = nt * 8 + g;
            int k0 = kt * 8 + a;
            float f0 = (n < DC - 1) ? beta[n * DZ + k0]     : 0.0f;
            float f1 = (n < DC - 1) ? beta[n * DZ + k0 + 4] : 0.0f;
            bf[kt][nt][0] = to_tf32(f0);
            bf[kt][nt][1] = to_tf32(f1);
        }

    const int numTiles = (T + TILE - 1) / TILE;
    int tile = blockIdx.x;
    if (tile >= numTiles) return;

    // cp.async staging of one z tile into buffer `buf`
    auto stage = [&](int t, int buf) {
        const int rows = min(TILE, T - t * TILE);
        const float4* src = reinterpret_cast<const float4*>(Z + (size_t)t * TILE * DZ);
        const int n4 = rows * (DZ / 4);
        for (int i = tid; i < n4; i += THREADS) {
            int r = i >> 4, c4 = i & 15;
            uint32_t dst = (uint32_t)__cvta_generic_to_shared(
                &zs[buf][r * ZS_STRIDE + c4 * 4]);
            asm volatile("cp.async.cg.shared.global [%0], [%1], 16;"
                         :: "r"(dst), "l"(src + i));
        }
        asm volatile("cp.async.commit_group;");
    };

    stage(tile, 0);
    int cur = 0;

    const int r0loc = w * 16 + g;    // this lane's base row within the tile

#pragma unroll 1
    for (; tile < numTiles; tile += gridDim.x) {
        const int nextTile = tile + gridDim.x;
        const bool hasNext = nextTile < numTiles;
        if (hasNext) stage(nextTile, cur ^ 1);      // prefetch into other buffer
        if (hasNext) asm volatile("cp.async.wait_group 1;" ::: "memory");
        else         asm volatile("cp.async.wait_group 0;" ::: "memory");
        __syncthreads();                            // tile `cur` visible to all

        const float* zb = zs[cur];
        const int tileBase = tile * TILE;

        // ---- mainloop: per-warp 16x32x64 GEMM via tf32 mma ----
        float C[4][4];
#pragma unroll
        for (int nt = 0; nt < 4; nt++)
#pragma unroll
            for (int j = 0; j < 4; j++) C[nt][j] = 0.0f;

#pragma unroll
        for (int kt = 0; kt < 8; kt++) {
            const int k0 = kt * 8 + a;
            uint32_t a0 = to_tf32(zb[r0loc * ZS_STRIDE + k0]);
            uint32_t a1 = to_tf32(zb[(r0loc + 8) * ZS_STRIDE + k0]);
            uint32_t a2 = to_tf32(zb[r0loc * ZS_STRIDE + k0 + 4]);
            uint32_t a3 = to_tf32(zb[(r0loc + 8) * ZS_STRIDE + k0 + 4]);
#pragma unroll
            for (int nt = 0; nt < 4; nt++)
                MMA_TF32(C[nt], a0, a1, a2, a3, bf[kt][nt][0], bf[kt][nt][1]);
        }

        // ---- epilogue: 2 row-slots (h), argmax + ambiguity flagging ----
        int idxs[2];
        unsigned flagm[2];
#pragma unroll
        for (int h = 0; h < 2; h++) {
            float best = C[0][h * 2];
            int   bch  = 2 * a;
#pragma unroll
            for (int nt = 0; nt < 4; nt++)
#pragma unroll
                for (int j = 0; j < 2; j++) {
                    float v = C[nt][h * 2 + j];
                    int  ch = nt * 8 + 2 * a + j;
                    if (v > best) { best = v; bch = ch; }
                }
#pragma unroll
            for (int off = 1; off <= 2; off <<= 1) {
                float ov = __shfl_xor_sync(0xffffffffu, best, off);
                int   oc = __shfl_xor_sync(0xffffffffu, bch,  off);
                if (ov > best) { best = ov; bch = oc; }
            }
            int cnt = 0;
            const float th = best - TH_FAST;
#pragma unroll
            for (int nt = 0; nt < 4; nt++)
#pragma unroll
                for (int j = 0; j < 2; j++)
                    cnt += (C[nt][h * 2 + j] >= th);
            cnt += __shfl_xor_sync(0xffffffffu, cnt, 1);
            cnt += __shfl_xor_sync(0xffffffffu, cnt, 2);

            idxs[h]  = bch;
            flagm[h] = __ballot_sync(0xffffffffu, cnt > 1);
        }

        // ---- re-decide flagged rows (exact-fp32, then exact-double) ----
#pragma unroll 1
        for (int h = 0; h < 2; h++) {
            unsigned m = flagm[h] & 0x11111111u;   // one bit per quad
#pragma unroll 1
            while (m) {
                const int b = __ffs(m) - 1;
                m &= m - 1;
                const int q    = b >> 2;
                const int rloc = w * 16 + q + h * 8;
                const int gr   = tileBase + rloc;
                if (gr >= T) continue;

                const float* zrow = &zb[rloc * ZS_STRIDE];

                float l = 0.0f;
                if (lane < DC - 1) {
                    const float* br = &bs[lane * BS_STRIDE];
                    float s0 = 0.0f, s1 = 0.0f;
#pragma unroll
                    for (int q2 = 0; q2 < 16; q2++) {
                        float4 zq = *reinterpret_cast<const float4*>(&zrow[4 * q2]);
                        s0 = fmaf(zq.x, br[4 * q2 + 0], s0);
                        s1 = fmaf(zq.y, br[4 * q2 + 1], s1);
                        s0 = fmaf(zq.z, br[4 * q2 + 2], s0);
                        s1 = fmaf(zq.w, br[4 * q2 + 3], s1);
                    }
                    l = s0 + s1;
                }
                unsigned u = __float_as_uint(l);
                u = (u & 0x80000000u) ? ~u : (u | 0x80000000u);
                unsigned umax;
                asm("redux.sync.max.u32 %0, %1, 0xffffffff;" : "=r"(umax) : "r"(u));
                const float mx = (umax & 0x80000000u)
                                   ? __uint_as_float(umax ^ 0x80000000u)
                                   : __uint_as_float(~umax);
                const unsigned nearMask = __ballot_sync(0xffffffffu, l >= mx - TH_MED);
                int idx;
                if (__popc(nearMask) == 1) {
                    idx = __ffs(nearMask) - 1;
                } else {
                    idx = decide_exact(zrow, bs, lane);
                }
                if (g == q) idxs[h] = idx;
            }
        }

        // ---- one-hot stores: quad-parallel STG.64 ----
#pragma unroll
        for (int h = 0; h < 2; h++) {
            const int rloc = w * 16 + g + h * 8;
            const int gr   = tileBase + rloc;
            if (gr < T) {
                float* o = out + (size_t)gr * DC + 2 * a;
#pragma unroll
                for (int nt = 0; nt < 4; nt++) {
                    const int ch0 = nt * 8 + 2 * a;
                    float2 v;
                    v.x = (ch0     == idxs[h]) ? 1.0f : 0.0f;
                    v.y = (ch0 + 1 == idxs[h]) ? 1.0f : 0.0f;
                    *reinterpret_cast<float2*>(o + nt * 8) = v;
                }
            }
        }

        __syncthreads();          // protect buf[cur] before next prefetch reuses it
        cur ^= 1;
    }
}

extern "C" void kernel_launch(void* const* d_in, const int* in_sizes, int n_in,
                              void* d_out, int out_size)
{
    const float* Z    = (const float*)d_in[0];
    const float* beta = (const float*)d_in[1];
    float* out        = (float*)d_out;

    const int T = in_sizes[0] / DZ;

    dec_cat_kernel<<<GRID, THREADS>>>(Z, beta, out, T);
}

// round 10
// speedup vs baseline: 2.2885x; 2.2885x over previous
#include <cuda_runtime.h>
#include <math.h>
#include <stdint.h>

#define DZ 64
#define DC 32
#define TILE 128
#define THREADS 128
#define ZS_STRIDE 68          // floats/row: conflict-free frag loads
#define BS_STRIDE 65          // padded beta row: conflict-free bs[c*65+d] reads
#define TH_FAST 2.5e-4f       // tf32 -> exact-fp32 re-decide trigger (proven R7/R8)
#define TH_MED  4e-6f         // fp32 -> exact-double re-decide trigger (proven R6-R8)

__device__ __forceinline__ uint32_t to_tf32(float f) {
    uint32_t r;
    asm("cvt.rna.tf32.f32 %0, %1;" : "=r"(r) : "f"(f));
    return r;
}

#define MMA_TF32(C, a0, a1, a2, a3, b0, b1)                                   \
    asm("mma.sync.aligned.m16n8k8.row.col.f32.tf32.tf32.f32 "                 \
        "{%0,%1,%2,%3}, {%4,%5,%6,%7}, {%8,%9}, {%0,%1,%2,%3};"               \
        : "+f"(C[0]), "+f"(C[1]), "+f"(C[2]), "+f"(C[3])                      \
        : "r"(a0), "r"(a1), "r"(a2), "r"(a3), "r"(b0), "r"(b1))

// Cold path: exact reference emulation (proven R3/R6/R7/R8).
//   double accumulate -> fp32 -> exp -> sequential norm -> IEEE divide
//   -> first-index argmax over probs.
__device__ __noinline__ int decide_exact(const float* __restrict__ zrow,
                                         const float* __restrict__ bs,
                                         int lane)
{
    int bi = 0;
    if (lane == 0) {
        float e[DC];
#pragma unroll 1
        for (int c = 0; c < DC - 1; c++) {
            double sd = 0.0;
#pragma unroll 1
            for (int d = 0; d < DZ; d++)
                sd += (double)zrow[d] * (double)bs[c * BS_STRIDE + d];
            float lf = (float)sd;
            e[c] = (float)exp((double)lf);
        }
        e[DC - 1] = 1.0f;
        float se = e[0];
#pragma unroll 1
        for (int c = 1; c < DC - 1; c++) se += e[c];
        const float norm = 1.0f + se;
        float pb = -1.0f;
#pragma unroll 1
        for (int c = 0; c < DC; c++) {
            float p = __fdiv_rn(e[c], norm);
            if (p > pb) { pb = p; bi = c; }   // strict > = first index
        }
    }
    return __shfl_sync(0xffffffffu, bi, 0);
}

__global__ __launch_bounds__(THREADS, 4)
void dec_cat_kernel(const float* __restrict__ Z,
                    const float* __restrict__ beta,
                    float* __restrict__ out,
                    int T)
{
    __shared__ float zs[TILE * ZS_STRIDE];       // exact fp32 z tile (padded)
    __shared__ float bs[(DC - 1) * BS_STRIDE];   // exact fp32 beta, padded rows

    const int tid  = threadIdx.x;
    const int lane = tid & 31;
    const int w    = tid >> 5;
    const int a    = lane & 3;    // threadID in group
    const int g    = lane >> 2;   // groupID (quad)
    const int rowBase = blockIdx.x * TILE;

    // ---- (1) z tile staged FIRST via cp.async: DRAM latency overlaps the
    //      beta copy and fragment build below ----
    {
        const int rowsHere = min(TILE, T - rowBase);
        const float4* Z4 = reinterpret_cast<const float4*>(Z + (size_t)rowBase * DZ);
        const int n4 = rowsHere * (DZ / 4);
        for (int i = tid; i < n4; i += THREADS) {
            int r = i >> 4, c4 = i & 15;
            uint32_t dst = (uint32_t)__cvta_generic_to_shared(
                &zs[r * ZS_STRIDE + c4 * 4]);
            asm volatile("cp.async.cg.shared.global [%0], [%1], 16;"
                         :: "r"(dst), "l"(Z4 + i));
        }
        asm volatile("cp.async.commit_group;" ::: "memory");
    }

    // ---- (2) exact beta copy (coalesced) for frag build + fallback paths ----
    for (int i = tid; i < (DC - 1) * DZ; i += THREADS)
        bs[(i >> 6) * BS_STRIDE + (i & 63)] = beta[i];
    __syncthreads();     // bs visible

    // ---- (3) B fragments (tf32) from SMEM: <=4-way bank conflicts instead of
    //      32-line L1 replay storms from scattered global loads ----
    uint32_t bf[8][4][2];
#pragma unroll
    for (int kt = 0; kt < 8; kt++)
#pragma unroll
        for (int nt = 0; nt < 4; nt++) {
            int n  = nt * 8 + g;
            int k0 = kt * 8 + a;
            float f0 = (n < DC - 1) ? bs[n * BS_STRIDE + k0]     : 0.0f;
            float f1 = (n < DC - 1) ? bs[n * BS_STRIDE + k0 + 4] : 0.0f;
            bf[kt][nt][0] = to_tf32(f0);
            bf[kt][nt][1] = to_tf32(f1);
        }

    // ---- z arrival ----
    asm volatile("cp.async.wait_group 0;" ::: "memory");
    __syncthreads();     // zs visible to all

    const int rw0 = w * 32;      // warp's 32-row sub-tile

    // ---- mainloop: 32x32x64 warp GEMM via tf32 mma (proven R7/R8) ----
    float C[2][4][4];
#pragma unroll
    for (int mt = 0; mt < 2; mt++)
#pragma unroll
        for (int nt = 0; nt < 4; nt++)
#pragma unroll
            for (int j = 0; j < 4; j++) C[mt][nt][j] = 0.0f;

#pragma unroll
    for (int kt = 0; kt < 8; kt++) {
        const int k0 = kt * 8 + a;
#pragma unroll
        for (int mt = 0; mt < 2; mt++) {
            const int r0 = rw0 + mt * 16 + g;
            uint32_t a0 = to_tf32(zs[r0 * ZS_STRIDE + k0]);
            uint32_t a1 = to_tf32(zs[(r0 + 8) * ZS_STRIDE + k0]);
            uint32_t a2 = to_tf32(zs[r0 * ZS_STRIDE + k0 + 4]);
            uint32_t a3 = to_tf32(zs[(r0 + 8) * ZS_STRIDE + k0 + 4]);
#pragma unroll
            for (int nt = 0; nt < 4; nt++)
                MMA_TF32(C[mt][nt], a0, a1, a2, a3, bf[kt][nt][0], bf[kt][nt][1]);
        }
    }

    // ---- epilogue: per row-slot argmax + ambiguity flagging (proven R7/R8) ----
    int idxs[4];
    unsigned flagm[4];
#pragma unroll
    for (int s = 0; s < 4; s++) {
        const int mt = s >> 1, h = s & 1;
        float best = C[mt][0][h * 2];
        int   bch  = 2 * a;
#pragma unroll
        for (int nt = 0; nt < 4; nt++)
#pragma unroll
            for (int j = 0; j < 2; j++) {
                float v = C[mt][nt][h * 2 + j];
                int  ch = nt * 8 + 2 * a + j;
                if (v > best) { best = v; bch = ch; }
            }
#pragma unroll
        for (int off = 1; off <= 2; off <<= 1) {
            float ov = __shfl_xor_sync(0xffffffffu, best, off);
            int   oc = __shfl_xor_sync(0xffffffffu, bch,  off);
            if (ov > best) { best = ov; bch = oc; }
        }
        int cnt = 0;
        const float th = best - TH_FAST;
#pragma unroll
        for (int nt = 0; nt < 4; nt++)
#pragma unroll
            for (int j = 0; j < 2; j++)
                cnt += (C[mt][nt][h * 2 + j] >= th);
        cnt += __shfl_xor_sync(0xffffffffu, cnt, 1);
        cnt += __shfl_xor_sync(0xffffffffu, cnt, 2);

        idxs[s]  = bch;
        flagm[s] = __ballot_sync(0xffffffffu, cnt > 1);
    }

    // ---- re-decide flagged rows (medium exact-fp32, then exact-double) ----
#pragma unroll 1
    for (int s = 0; s < 4; s++) {
        unsigned m = flagm[s] & 0x11111111u;   // one representative bit per quad
#pragma unroll 1
        while (m) {
            const int b = __ffs(m) - 1;
            m &= m - 1;
            const int q    = b >> 2;
            const int rloc = (s >> 1) * 16 + q + (s & 1) * 8;
            const int gr   = rowBase + rw0 + rloc;
            if (gr >= T) continue;

            const float* zrow = &zs[(rw0 + rloc) * ZS_STRIDE];   // THIS warp's row

            // lane = channel; exact fp32 z + exact fp32 beta (conflict-free)
            float l = 0.0f;
            if (lane < DC - 1) {
                const float* br = &bs[lane * BS_STRIDE];
                float s0 = 0.0f, s1 = 0.0f;
#pragma unroll
                for (int q2 = 0; q2 < 16; q2++) {
                    float4 zq = *reinterpret_cast<const float4*>(&zrow[4 * q2]);
                    s0 = fmaf(zq.x, br[4 * q2 + 0], s0);
                    s1 = fmaf(zq.y, br[4 * q2 + 1], s1);
                    s0 = fmaf(zq.z, br[4 * q2 + 2], s0);
                    s1 = fmaf(zq.w, br[4 * q2 + 3], s1);
                }
                l = s0 + s1;
            }
            unsigned u = __float_as_uint(l);
            u = (u & 0x80000000u) ? ~u : (u | 0x80000000u);
            unsigned umax;
            asm("redux.sync.max.u32 %0, %1, 0xffffffff;" : "=r"(umax) : "r"(u));
            const float mx = (umax & 0x80000000u)
                               ? __uint_as_float(umax ^ 0x80000000u)
                               : __uint_as_float(~umax);
            const unsigned nearMask = __ballot_sync(0xffffffffu, l >= mx - TH_MED);
            int idx;
            if (__popc(nearMask) == 1) {
                idx = __ffs(nearMask) - 1;
            } else {
                idx = decide_exact(zrow, bs, lane);
            }
            if (g == q) idxs[s] = idx;   // owning quad adopts the decision
        }
    }

    // ---- one-hot stores: 4 x STG.64 per slot (quad-parallel) ----
#pragma unroll
    for (int s = 0; s < 4; s++) {
        const int rloc = (s >> 1) * 16 + g + (s & 1) * 8;
        const int gr   = rowBase + rw0 + rloc;
        if (gr < T) {
            float* o = out + (size_t)gr * DC + 2 * a;
#pragma unroll
            for (int nt = 0; nt < 4; nt++) {
                const int ch0 = nt * 8 + 2 * a;
                float2 v;
                v.x = (ch0     == idxs[s]) ? 1.0f : 0.0f;
                v.y = (ch0 + 1 == idxs[s]) ? 1.0f : 0.0f;
                *reinterpret_cast<float2*>(o + nt * 8) = v;
            }
        }
    }
}

extern "C" void kernel_launch(void* const* d_in, const int* in_sizes, int n_in,
                              void* d_out, int out_size)
{
    const float* Z    = (const float*)d_in[0];
    const float* beta = (const float*)d_in[1];
    float* out        = (float*)d_out;

    const int T = in_sizes[0] / DZ;
    const int grid = (T + TILE - 1) / TILE;

    dec_cat_kernel<<<grid, THREADS>>>(Z, beta, out, T);
}

// round 11
// speedup vs baseline: 2.4130x; 1.0544x over previous
#include <cuda_runtime.h>
#include <math.h>
#include <stdint.h>

#define DZ 64
#define DC 32
#define TILE 128
#define THREADS 128
#define ZS_STRIDE 68          // floats/row: conflict-free A-frag loads
#define BS_STRIDE 68          // 68%32=4 -> bank(4g+a) all-distinct for B loads
#define TH_FAST 2.5e-4f       // tf32 -> exact-fp32 re-decide trigger (proven R7-R10)
#define TH_MED  4e-6f         // fp32 -> exact-double re-decide trigger (proven R6-R10)

__device__ __forceinline__ uint32_t to_tf32(float f) {
    uint32_t r;
    asm("cvt.rna.tf32.f32 %0, %1;" : "=r"(r) : "f"(f));
    return r;
}

#define MMA_TF32(C, a0, a1, a2, a3, b0, b1)                                   \
    asm("mma.sync.aligned.m16n8k8.row.col.f32.tf32.tf32.f32 "                 \
        "{%0,%1,%2,%3}, {%4,%5,%6,%7}, {%8,%9}, {%0,%1,%2,%3};"               \
        : "+f"(C[0]), "+f"(C[1]), "+f"(C[2]), "+f"(C[3])                      \
        : "r"(a0), "r"(a1), "r"(a2), "r"(a3), "r"(b0), "r"(b1))

// Cold path: exact reference emulation (proven R3/R6-R10).
//   double accumulate -> fp32 -> exp -> sequential norm -> IEEE divide
//   -> first-index argmax over probs.
__device__ __noinline__ int decide_exact(const float* __restrict__ zrow,
                                         const float* __restrict__ bs,
                                         int lane)
{
    int bi = 0;
    if (lane == 0) {
        float e[DC];
#pragma unroll 1
        for (int c = 0; c < DC - 1; c++) {
            double sd = 0.0;
#pragma unroll 1
            for (int d = 0; d < DZ; d++)
                sd += (double)zrow[d] * (double)bs[c * BS_STRIDE + d];
            float lf = (float)sd;
            e[c] = (float)exp((double)lf);
        }
        e[DC - 1] = 1.0f;
        float se = e[0];
#pragma unroll 1
        for (int c = 1; c < DC - 1; c++) se += e[c];
        const float norm = 1.0f + se;
        float pb = -1.0f;
#pragma unroll 1
        for (int c = 0; c < DC; c++) {
            float p = __fdiv_rn(e[c], norm);
            if (p > pb) { pb = p; bi = c; }   // strict > = first index
        }
    }
    return __shfl_sync(0xffffffffu, bi, 0);
}

__global__ __launch_bounds__(THREADS, 5)
void dec_cat_kernel(const float* __restrict__ Z,
                    const float* __restrict__ beta,
                    float* __restrict__ out,
                    int T)
{
    __shared__ float zs[TILE * ZS_STRIDE];       // exact fp32 z tile (34 KB)
    __shared__ float bs[(DC - 1) * BS_STRIDE];   // exact fp32 beta (8.5 KB)

    const int tid  = threadIdx.x;
    const int lane = tid & 31;
    const int w    = tid >> 5;
    const int a    = lane & 3;    // threadID in group
    const int g    = lane >> 2;   // groupID (quad)
    const int rowBase = blockIdx.x * TILE;

    // ---- (1) z tile via cp.async FIRST: DRAM latency overlaps beta copy ----
    {
        const int rowsHere = min(TILE, T - rowBase);
        const float4* Z4 = reinterpret_cast<const float4*>(Z + (size_t)rowBase * DZ);
        const int n4 = rowsHere * (DZ / 4);
        for (int i = tid; i < n4; i += THREADS) {
            int r = i >> 4, c4 = i & 15;
            uint32_t dst = (uint32_t)__cvta_generic_to_shared(
                &zs[r * ZS_STRIDE + c4 * 4]);
            asm volatile("cp.async.cg.shared.global [%0], [%1], 16;"
                         :: "r"(dst), "l"(Z4 + i));
        }
        asm volatile("cp.async.commit_group;" ::: "memory");
    }

    // ---- (2) exact beta copy (coalesced LDG, L2-hot) ----
    for (int i = tid; i < (DC - 1) * DZ; i += THREADS)
        bs[(i >> 6) * BS_STRIDE + (i & 63)] = beta[i];

    // ---- (3) single rendezvous: z arrived + bs visible ----
    asm volatile("cp.async.wait_group 0;" ::: "memory");
    __syncthreads();

    const int rw0 = w * 32;      // warp's 32-row sub-tile

    // ---- mainloop: 32x32x64 warp GEMM; B loaded per-kt from smem (no 64-reg
    //      fragment array -> 5 blocks/SM resident) ----
    float C[2][4][4];
#pragma unroll
    for (int mt = 0; mt < 2; mt++)
#pragma unroll
        for (int nt = 0; nt < 4; nt++)
#pragma unroll
            for (int j = 0; j < 4; j++) C[mt][nt][j] = 0.0f;

#pragma unroll
    for (int kt = 0; kt < 8; kt++) {
        const int k0 = kt * 8 + a;

        // B fragments for this kt: conflict-free (bank = 4g+a+const, distinct)
        uint32_t b0[4], b1[4];
#pragma unroll
        for (int nt = 0; nt < 4; nt++) {
            const int n = nt * 8 + g;
            float f0 = (n < DC - 1) ? bs[n * BS_STRIDE + k0]     : 0.0f;
            float f1 = (n < DC - 1) ? bs[n * BS_STRIDE + k0 + 4] : 0.0f;
            b0[nt] = to_tf32(f0);
            b1[nt] = to_tf32(f1);
        }

#pragma unroll
        for (int mt = 0; mt < 2; mt++) {
            const int r0 = rw0 + mt * 16 + g;
            uint32_t a0 = to_tf32(zs[r0 * ZS_STRIDE + k0]);
            uint32_t a1 = to_tf32(zs[(r0 + 8) * ZS_STRIDE + k0]);
            uint32_t a2 = to_tf32(zs[r0 * ZS_STRIDE + k0 + 4]);
            uint32_t a3 = to_tf32(zs[(r0 + 8) * ZS_STRIDE + k0 + 4]);
#pragma unroll
            for (int nt = 0; nt < 4; nt++)
                MMA_TF32(C[mt][nt], a0, a1, a2, a3, b0[nt], b1[nt]);
        }
    }

    // ---- epilogue: per row-slot argmax + ambiguity flagging (proven R7-R10) ----
    int idxs[4];
    unsigned flagm[4];
#pragma unroll
    for (int s = 0; s < 4; s++) {
        const int mt = s >> 1, h = s & 1;
        float best = C[mt][0][h * 2];
        int   bch  = 2 * a;
#pragma unroll
        for (int nt = 0; nt < 4; nt++)
#pragma unroll
            for (int j = 0; j < 2; j++) {
                float v = C[mt][nt][h * 2 + j];
                int  ch = nt * 8 + 2 * a + j;
                if (v > best) { best = v; bch = ch; }
            }
#pragma unroll
        for (int off = 1; off <= 2; off <<= 1) {
            float ov = __shfl_xor_sync(0xffffffffu, best, off);
            int   oc = __shfl_xor_sync(0xffffffffu, bch,  off);
            if (ov > best) { best = ov; bch = oc; }
        }
        int cnt = 0;
        const float th = best - TH_FAST;
#pragma unroll
        for (int nt = 0; nt < 4; nt++)
#pragma unroll
            for (int j = 0; j < 2; j++)
                cnt += (C[mt][nt][h * 2 + j] >= th);
        cnt += __shfl_xor_sync(0xffffffffu, cnt, 1);
        cnt += __shfl_xor_sync(0xffffffffu, cnt, 2);

        idxs[s]  = bch;
        flagm[s] = __ballot_sync(0xffffffffu, cnt > 1);
    }

    // ---- re-decide flagged rows (medium exact-fp32, then exact-double) ----
#pragma unroll 1
    for (int s = 0; s < 4; s++) {
        unsigned m = flagm[s] & 0x11111111u;   // one representative bit per quad
#pragma unroll 1
        while (m) {
            const int b = __ffs(m) - 1;
            m &= m - 1;
            const int q    = b >> 2;
            const int rloc = (s >> 1) * 16 + q + (s & 1) * 8;
            const int gr   = rowBase + rw0 + rloc;
            if (gr >= T) continue;

            const float* zrow = &zs[(rw0 + rloc) * ZS_STRIDE];   // THIS warp's row

            // lane = channel; exact fp32 z + exact fp32 beta
            float l = 0.0f;
            if (lane < DC - 1) {
                const float* br = &bs[lane * BS_STRIDE];
                float s0 = 0.0f, s1 = 0.0f;
#pragma unroll
                for (int q2 = 0; q2 < 16; q2++) {
                    float4 zq = *reinterpret_cast<const float4*>(&zrow[4 * q2]);
                    s0 = fmaf(zq.x, br[4 * q2 + 0], s0);
                    s1 = fmaf(zq.y, br[4 * q2 + 1], s1);
                    s0 = fmaf(zq.z, br[4 * q2 + 2], s0);
                    s1 = fmaf(zq.w, br[4 * q2 + 3], s1);
                }
                l = s0 + s1;
            }
            unsigned u = __float_as_uint(l);
            u = (u & 0x80000000u) ? ~u : (u | 0x80000000u);
            unsigned umax;
            asm("redux.sync.max.u32 %0, %1, 0xffffffff;" : "=r"(umax) : "r"(u));
            const float mx = (umax & 0x80000000u)
                               ? __uint_as_float(umax ^ 0x80000000u)
                               : __uint_as_float(~umax);
            const unsigned nearMask = __ballot_sync(0xffffffffu, l >= mx - TH_MED);
            int idx;
            if (__popc(nearMask) == 1) {
                idx = __ffs(nearMask) - 1;
            } else {
                idx = decide_exact(zrow, bs, lane);
            }
            if (g == q) idxs[s] = idx;   // owning quad adopts the decision
        }
    }

    // ---- one-hot stores: 4 x STG.64 per slot (quad-parallel) ----
#pragma unroll
    for (int s = 0; s < 4; s++) {
        const int rloc = (s >> 1) * 16 + g + (s & 1) * 8;
        const int gr   = rowBase + rw0 + rloc;
        if (gr < T) {
            float* o = out + (size_t)gr * DC + 2 * a;
#pragma unroll
            for (int nt = 0; nt < 4; nt++) {
                const int ch0 = nt * 8 + 2 * a;
                float2 v;
                v.x = (ch0     == idxs[s]) ? 1.0f : 0.0f;
                v.y = (ch0 + 1 == idxs[s]) ? 1.0f : 0.0f;
                *reinterpret_cast<float2*>(o + nt * 8) = v;
            }
        }
    }
}

extern "C" void kernel_launch(void* const* d_in, const int* in_sizes, int n_in,
                              void* d_out, int out_size)
{
    const float* Z    = (const float*)d_in[0];
    const float* beta = (const float*)d_in[1];
    float* out        = (float*)d_out;

    const int T = in_sizes[0] / DZ;
    const int grid = (T + TILE - 1) / TILE;

    dec_cat_kernel<<<grid, THREADS>>>(Z, beta, out, T);
}

// round 12
// speedup vs baseline: 2.4771x; 1.0266x over previous
#include <cuda_runtime.h>
#include <math.h>
#include <stdint.h>

#define DZ 64
#define DC 32
#define TILE 128
#define THREADS 256
#define ZS_STRIDE 68          // floats/row: conflict-free A-frag loads
#define BS_STRIDE 68          // bank(4g+a) all-distinct for B loads
#define TH_FAST 2.5e-4f       // tf32 -> exact-fp32 re-decide trigger (proven R7-R11)
#define TH_MED  4e-6f         // fp32 -> exact-double re-decide trigger (proven R6-R11)

__device__ __forceinline__ uint32_t to_tf32(float f) {
    uint32_t r;
    asm("cvt.rna.tf32.f32 %0, %1;" : "=r"(r) : "f"(f));
    return r;
}

#define MMA_TF32(C, a0, a1, a2, a3, b0, b1)                                   \
    asm("mma.sync.aligned.m16n8k8.row.col.f32.tf32.tf32.f32 "                 \
        "{%0,%1,%2,%3}, {%4,%5,%6,%7}, {%8,%9}, {%0,%1,%2,%3};"               \
        : "+f"(C[0]), "+f"(C[1]), "+f"(C[2]), "+f"(C[3])                      \
        : "r"(a0), "r"(a1), "r"(a2), "r"(a3), "r"(b0), "r"(b1))

// Cold path: exact reference emulation (proven R3/R6-R11).
//   double accumulate -> fp32 -> exp -> sequential norm -> IEEE divide
//   -> first-index argmax over probs.
__device__ __noinline__ int decide_exact(const float* __restrict__ zrow,
                                         const float* __restrict__ bs,
                                         int lane)
{
    int bi = 0;
    if (lane == 0) {
        float e[DC];
#pragma unroll 1
        for (int c = 0; c < DC - 1; c++) {
            double sd = 0.0;
#pragma unroll 1
            for (int d = 0; d < DZ; d++)
                sd += (double)zrow[d] * (double)bs[c * BS_STRIDE + d];
            float lf = (float)sd;
            e[c] = (float)exp((double)lf);
        }
        e[DC - 1] = 1.0f;
        float se = e[0];
#pragma unroll 1
        for (int c = 1; c < DC - 1; c++) se += e[c];
        const float norm = 1.0f + se;
        float pb = -1.0f;
#pragma unroll 1
        for (int c = 0; c < DC; c++) {
            float p = __fdiv_rn(e[c], norm);
            if (p > pb) { pb = p; bi = c; }   // strict > = first index
        }
    }
    return __shfl_sync(0xffffffffu, bi, 0);
}

__global__ __launch_bounds__(THREADS, 4)
void dec_cat_kernel(const float* __restrict__ Z,
                    const float* __restrict__ beta,
                    float* __restrict__ out,
                    int T)
{
    __shared__ float zs[TILE * ZS_STRIDE];       // exact fp32 z tile (34 KB)
    __shared__ float bs[(DC - 1) * BS_STRIDE];   // exact fp32 beta (8.5 KB)

    const int tid  = threadIdx.x;
    const int lane = tid & 31;
    const int w    = tid >> 5;    // 8 warps
    const int a    = lane & 3;    // threadID in group
    const int g    = lane >> 2;   // groupID (quad)
    const int rowBase = blockIdx.x * TILE;

    // ---- (1) z tile via cp.async FIRST: DRAM latency overlaps beta copy ----
    {
        const int rowsHere = min(TILE, T - rowBase);
        const float4* Z4 = reinterpret_cast<const float4*>(Z + (size_t)rowBase * DZ);
        const int n4 = rowsHere * (DZ / 4);
        for (int i = tid; i < n4; i += THREADS) {
            int r = i >> 4, c4 = i & 15;
            uint32_t dst = (uint32_t)__cvta_generic_to_shared(
                &zs[r * ZS_STRIDE + c4 * 4]);
            asm volatile("cp.async.cg.shared.global [%0], [%1], 16;"
                         :: "r"(dst), "l"(Z4 + i));
        }
        asm volatile("cp.async.commit_group;" ::: "memory");
    }

    // ---- (2) exact beta copy (coalesced LDG, L2-hot) ----
    for (int i = tid; i < (DC - 1) * DZ; i += THREADS)
        bs[(i >> 6) * BS_STRIDE + (i & 63)] = beta[i];

    // ---- (3) single rendezvous: z arrived + bs visible ----
    asm volatile("cp.async.wait_group 0;" ::: "memory");
    __syncthreads();

    const int rw0 = w * 16;      // this warp's 16-row m-tile

    // ---- mainloop: 16x32x64 warp GEMM; B loaded per-kt from smem ----
    float C[4][4];
#pragma unroll
    for (int nt = 0; nt < 4; nt++)
#pragma unroll
        for (int j = 0; j < 4; j++) C[nt][j] = 0.0f;

#pragma unroll
    for (int kt = 0; kt < 8; kt++) {
        const int k0 = kt * 8 + a;

        // B fragments for this kt: conflict-free (bank = 4g+a+const, distinct)
        uint32_t b0[4], b1[4];
#pragma unroll
        for (int nt = 0; nt < 4; nt++) {
            const int n = nt * 8 + g;
            float f0 = (n < DC - 1) ? bs[n * BS_STRIDE + k0]     : 0.0f;
            float f1 = (n < DC - 1) ? bs[n * BS_STRIDE + k0 + 4] : 0.0f;
            b0[nt] = to_tf32(f0);
            b1[nt] = to_tf32(f1);
        }

        const int r0 = rw0 + g;
        uint32_t a0 = to_tf32(zs[r0 * ZS_STRIDE + k0]);
        uint32_t a1 = to_tf32(zs[(r0 + 8) * ZS_STRIDE + k0]);
        uint32_t a2 = to_tf32(zs[r0 * ZS_STRIDE + k0 + 4]);
        uint32_t a3 = to_tf32(zs[(r0 + 8) * ZS_STRIDE + k0 + 4]);
#pragma unroll
        for (int nt = 0; nt < 4; nt++)
            MMA_TF32(C[nt], a0, a1, a2, a3, b0[nt], b1[nt]);
    }

    // ---- epilogue: 2 row-slots (h), argmax + ambiguity flagging ----
    int idxs[2];
    unsigned flagm[2];
#pragma unroll
    for (int h = 0; h < 2; h++) {
        float best = C[0][h * 2];
        int   bch  = 2 * a;
#pragma unroll
        for (int nt = 0; nt < 4; nt++)
#pragma unroll
            for (int j = 0; j < 2; j++) {
                float v = C[nt][h * 2 + j];
                int  ch = nt * 8 + 2 * a + j;
                if (v > best) { best = v; bch = ch; }
            }
#pragma unroll
        for (int off = 1; off <= 2; off <<= 1) {
            float ov = __shfl_xor_sync(0xffffffffu, best, off);
            int   oc = __shfl_xor_sync(0xffffffffu, bch,  off);
            if (ov > best) { best = ov; bch = oc; }
        }
        int cnt = 0;
        const float th = best - TH_FAST;
#pragma unroll
        for (int nt = 0; nt < 4; nt++)
#pragma unroll
            for (int j = 0; j < 2; j++)
                cnt += (C[nt][h * 2 + j] >= th);
        cnt += __shfl_xor_sync(0xffffffffu, cnt, 1);
        cnt += __shfl_xor_sync(0xffffffffu, cnt, 2);

        idxs[h]  = bch;
        flagm[h] = __ballot_sync(0xffffffffu, cnt > 1);
    }

    // ---- re-decide flagged rows (medium exact-fp32, then exact-double) ----
#pragma unroll 1
    for (int h = 0; h < 2; h++) {
        unsigned m = flagm[h] & 0x11111111u;   // one representative bit per quad
#pragma unroll 1
        while (m) {
            const int b = __ffs(m) - 1;
            m &= m - 1;
            const int q    = b >> 2;
            const int rloc = rw0 + q + h * 8;     // this warp's row in the tile
            const int gr   = rowBase + rloc;
            if (gr >= T) continue;

            const float* zrow = &zs[rloc * ZS_STRIDE];

            // lane = channel; exact fp32 z + exact fp32 beta
            float l = 0.0f;
            if (lane < DC - 1) {
                const float* br = &bs[lane * BS_STRIDE];
                float s0 = 0.0f, s1 = 0.0f;
#pragma unroll
                for (int q2 = 0; q2 < 16; q2++) {
                    float4 zq = *reinterpret_cast<const float4*>(&zrow[4 * q2]);
                    s0 = fmaf(zq.x, br[4 * q2 + 0], s0);
                    s1 = fmaf(zq.y, br[4 * q2 + 1], s1);
                    s0 = fmaf(zq.z, br[4 * q2 + 2], s0);
                    s1 = fmaf(zq.w, br[4 * q2 + 3], s1);
                }
                l = s0 + s1;
            }
            unsigned u = __float_as_uint(l);
            u = (u & 0x80000000u) ? ~u : (u | 0x80000000u);
            unsigned umax;
            asm("redux.sync.max.u32 %0, %1, 0xffffffff;" : "=r"(umax) : "r"(u));
            const float mx = (umax & 0x80000000u)
                               ? __uint_as_float(umax ^ 0x80000000u)
                               : __uint_as_float(~umax);
            const unsigned nearMask = __ballot_sync(0xffffffffu, l >= mx - TH_MED);
            int idx;
            if (__popc(nearMask) == 1) {
                idx = __ffs(nearMask) - 1;
            } else {
                idx = decide_exact(zrow, bs, lane);
            }
            if (g == q) idxs[h] = idx;   // owning quad adopts the decision
        }
    }

    // ---- one-hot stores: quad-parallel STG.64 ----
#pragma unroll
    for (int h = 0; h < 2; h++) {
        const int rloc = rw0 + g + h * 8;
        const int gr   = rowBase + rloc;
        if (gr < T) {
            float* o = out + (size_t)gr * DC + 2 * a;
#pragma unroll
            for (int nt = 0; nt < 4; nt++) {
                const int ch0 = nt * 8 + 2 * a;
                float2 v;
                v.x = (ch0     == idxs[h]) ? 1.0f : 0.0f;
                v.y = (ch0 + 1 == idxs[h]) ? 1.0f : 0.0f;
                *reinterpret_cast<float2*>(o + nt * 8) = v;
            }
        }
    }
}

extern "C" void kernel_launch(void* const* d_in, const int* in_sizes, int n_in,
                              void* d_out, int out_size)
{
    const float* Z    = (const float*)d_in[0];
    const float* beta = (const float*)d_in[1];
    float* out        = (float*)d_out;

    const int T = in_sizes[0] / DZ;
    const int grid = (T + TILE - 1) / TILE;

    dec_cat_kernel<<<grid, THREADS>>>(Z, beta, out, T);
}

// round 14
// speedup vs baseline: 2.5331x; 1.0226x over previous
#include <cuda_runtime.h>
#include <math.h>
#include <stdint.h>

#define DZ 64
#define DC 32
#define TILE 128
#define THREADS 256
#define ZS_STRIDE 68          // floats/row: conflict-free A-frag loads (4g+a distinct)
#define BS_STRIDE 68          // bank(4g+a) all-distinct for B loads
#define TH_FAST 2.5e-4f       // tf32 -> exact-fp32 re-decide trigger (proven R7-R12)
#define TH_MED  4e-6f         // fp32 -> exact-double re-decide trigger (proven R6-R12)

__device__ __forceinline__ uint32_t to_tf32(float f) {
    uint32_t r;
    asm("cvt.rna.tf32.f32 %0, %1;" : "=r"(r) : "f"(f));
    return r;
}

__device__ __forceinline__ uint32_t smem_u32(const void* p) {
    uint32_t addr;
    asm("{ .reg .u64 t; cvta.to.shared.u64 t, %1; cvt.u32.u64 %0, t; }"
        : "=r"(addr) : "l"(p));
    return addr;
}

#define MMA_TF32(C, a0, a1, a2, a3, b0, b1)                                   \
    asm("mma.sync.aligned.m16n8k8.row.col.f32.tf32.tf32.f32 "                 \
        "{%0,%1,%2,%3}, {%4,%5,%6,%7}, {%8,%9}, {%0,%1,%2,%3};"               \
        : "+f"(C[0]), "+f"(C[1]), "+f"(C[2]), "+f"(C[3])                      \
        : "r"(a0), "r"(a1), "r"(a2), "r"(a3), "r"(b0), "r"(b1))

// Cold path: exact reference emulation (proven R3/R6-R12).
__device__ __noinline__ int decide_exact(const float* __restrict__ zrow,
                                         const float* __restrict__ bs,
                                         int lane)
{
    int bi = 0;
    if (lane == 0) {
        float e[DC];
#pragma unroll 1
        for (int c = 0; c < DC - 1; c++) {
            double sd = 0.0;
#pragma unroll 1
            for (int d = 0; d < DZ; d++)
                sd += (double)zrow[d] * (double)bs[c * BS_STRIDE + d];
            float lf = (float)sd;
            e[c] = (float)exp((double)lf);
        }
        e[DC - 1] = 1.0f;
        float se = e[0];
#pragma unroll 1
        for (int c = 1; c < DC - 1; c++) se += e[c];
        const float norm = 1.0f + se;
        float pb = -1.0f;
#pragma unroll 1
        for (int c = 0; c < DC; c++) {
            float p = __fdiv_rn(e[c], norm);
            if (p > pb) { pb = p; bi = c; }   // strict > = first index
        }
    }
    return __shfl_sync(0xffffffffu, bi, 0);
}

__global__ __launch_bounds__(THREADS, 4)
void dec_cat_kernel(const float* __restrict__ Z,
                    const float* __restrict__ beta,
                    float* __restrict__ out,
                    int T)
{
    // alignas(128): cp.async.bulk needs 16B-aligned smem destinations; shared
    // frame placement is not declaration-ordered, so force it (R13 crash cause).
    __shared__ alignas(128) float zs[TILE * ZS_STRIDE];       // z tile (34 KB)
    __shared__ alignas(128) float bs[(DC - 1) * BS_STRIDE];   // beta (8.4 KB)
    __shared__ alignas(8) unsigned long long mbar;

    const int tid  = threadIdx.x;
    const int lane = tid & 31;
    const int w    = tid >> 5;    // 8 warps
    const int a    = lane & 3;    // threadID in group
    const int g    = lane >> 2;   // groupID (quad)
    const int rowBase = blockIdx.x * TILE;
    const int rowsHere = min(TILE, T - rowBase);

    const uint32_t mb = smem_u32(&mbar);

    // ---- staging: one 256B cp.async.bulk per row (z + beta), one mbarrier ----
    if (tid == 0) {
        asm volatile("mbarrier.init.shared.b64 [%0], 1;" :: "r"(mb) : "memory");
    }
    __syncthreads();
    if (tid == 0) {
        const uint32_t totalBytes = (uint32_t)rowsHere * 256u + (DC - 1) * 256u;
        asm volatile("mbarrier.arrive.expect_tx.shared.b64 _, [%0], %1;"
                     :: "r"(mb), "r"(totalBytes) : "memory");
    }
    __syncthreads();     // expect_tx visible before any complete_tx can land

    if (tid < rowsHere) {
        // z row tid -> zs[tid*68] (272B stride, 16B aligned from 128B base)
        uint32_t dst = smem_u32(&zs[tid * ZS_STRIDE]);
        const float* src = Z + (size_t)(rowBase + tid) * DZ;
        asm volatile(
            "cp.async.bulk.shared::cta.global.mbarrier::complete_tx::bytes "
            "[%0], [%1], 256, [%2];"
            :: "r"(dst), "l"(src), "r"(mb) : "memory");
    } else if (tid >= 128 && tid < 128 + DC - 1) {
        // beta row (tid-128) -> bs[(tid-128)*68]
        const int c = tid - 128;
        uint32_t dst = smem_u32(&bs[c * BS_STRIDE]);
        const float* src = beta + (size_t)c * DZ;
        asm volatile(
            "cp.async.bulk.shared::cta.global.mbarrier::complete_tx::bytes "
            "[%0], [%1], 256, [%2];"
            :: "r"(dst), "l"(src), "r"(mb) : "memory");
    }

    // wait for all bytes (parity 0)
    {
        uint32_t done;
        asm volatile(
            "{\n\t.reg .pred p;\n\t"
            "mbarrier.try_wait.parity.acquire.cta.shared::cta.b64 p, [%1], 0;\n\t"
            "selp.b32 %0, 1, 0, p;\n\t}"
            : "=r"(done) : "r"(mb) : "memory");
        if (!done) {
            asm volatile(
                "{\n\t.reg .pred P1;\n\t"
                "W_%=:\n\t"
                "mbarrier.try_wait.parity.acquire.cta.shared::cta.b64 P1, [%0], 0, 0x989680;\n\t"
                "@P1 bra.uni D_%=;\n\t"
                "bra.uni W_%=;\n\t"
                "D_%=:\n\t}"
                :: "r"(mb) : "memory");
        }
    }

    const int rw0 = w * 16;      // this warp's 16-row m-tile

    // ---- mainloop: 16x32x64 warp GEMM; B loaded per-kt from smem ----
    float C[4][4];
#pragma unroll
    for (int nt = 0; nt < 4; nt++)
#pragma unroll
        for (int j = 0; j < 4; j++) C[nt][j] = 0.0f;

#pragma unroll
    for (int kt = 0; kt < 8; kt++) {
        const int k0 = kt * 8 + a;

        uint32_t b0[4], b1[4];
#pragma unroll
        for (int nt = 0; nt < 4; nt++) {
            const int n = nt * 8 + g;
            float f0 = (n < DC - 1) ? bs[n * BS_STRIDE + k0]     : 0.0f;
            float f1 = (n < DC - 1) ? bs[n * BS_STRIDE + k0 + 4] : 0.0f;
            b0[nt] = to_tf32(f0);
            b1[nt] = to_tf32(f1);
        }

        const int r0 = rw0 + g;
        uint32_t a0 = to_tf32(zs[r0 * ZS_STRIDE + k0]);
        uint32_t a1 = to_tf32(zs[(r0 + 8) * ZS_STRIDE + k0]);
        uint32_t a2 = to_tf32(zs[r0 * ZS_STRIDE + k0 + 4]);
        uint32_t a3 = to_tf32(zs[(r0 + 8) * ZS_STRIDE + k0 + 4]);
#pragma unroll
        for (int nt = 0; nt < 4; nt++)
            MMA_TF32(C[nt], a0, a1, a2, a3, b0[nt], b1[nt]);
    }

    // ---- epilogue: 2 row-slots (h), argmax + ambiguity flagging (proven) ----
    int idxs[2];
    unsigned flagm[2];
#pragma unroll
    for (int h = 0; h < 2; h++) {
        float best = C[0][h * 2];
        int   bch  = 2 * a;
#pragma unroll
        for (int nt = 0; nt < 4; nt++)
#pragma unroll
            for (int j = 0; j < 2; j++) {
                float v = C[nt][h * 2 + j];
                int  ch = nt * 8 + 2 * a + j;
                if (v > best) { best = v; bch = ch; }
            }
#pragma unroll
        for (int off = 1; off <= 2; off <<= 1) {
            float ov = __shfl_xor_sync(0xffffffffu, best, off);
            int   oc = __shfl_xor_sync(0xffffffffu, bch,  off);
            if (ov > best) { best = ov; bch = oc; }
        }
        int cnt = 0;
        const float th = best - TH_FAST;
#pragma unroll
        for (int nt = 0; nt < 4; nt++)
#pragma unroll
            for (int j = 0; j < 2; j++)
                cnt += (C[nt][h * 2 + j] >= th);
        cnt += __shfl_xor_sync(0xffffffffu, cnt, 1);
        cnt += __shfl_xor_sync(0xffffffffu, cnt, 2);

        idxs[h]  = bch;
        flagm[h] = __ballot_sync(0xffffffffu, cnt > 1);
    }

    // ---- re-decide flagged rows (medium exact-fp32, then exact-double) ----
#pragma unroll 1
    for (int h = 0; h < 2; h++) {
        unsigned m = flagm[h] & 0x11111111u;   // one representative bit per quad
#pragma unroll 1
        while (m) {
            const int b = __ffs(m) - 1;
            m &= m - 1;
            const int q    = b >> 2;
            const int rloc = rw0 + q + h * 8;     // this warp's row in the tile
            const int gr   = rowBase + rloc;
            if (gr >= T) continue;

            const float* zrow = &zs[rloc * ZS_STRIDE];

            float l = 0.0f;
            if (lane < DC - 1) {
                const float* br = &bs[lane * BS_STRIDE];
                float s0 = 0.0f, s1 = 0.0f;
#pragma unroll
                for (int q2 = 0; q2 < 16; q2++) {
                    float4 zq = *reinterpret_cast<const float4*>(&zrow[4 * q2]);
                    s0 = fmaf(zq.x, br[4 * q2 + 0], s0);
                    s1 = fmaf(zq.y, br[4 * q2 + 1], s1);
                    s0 = fmaf(zq.z, br[4 * q2 + 2], s0);
                    s1 = fmaf(zq.w, br[4 * q2 + 3], s1);
                }
                l = s0 + s1;
            }
            unsigned u = __float_as_uint(l);
            u = (u & 0x80000000u) ? ~u : (u | 0x80000000u);
            unsigned umax;
            asm("redux.sync.max.u32 %0, %1, 0xffffffff;" : "=r"(umax) : "r"(u));
            const float mx = (umax & 0x80000000u)
                               ? __uint_as_float(umax ^ 0x80000000u)
                               : __uint_as_float(~umax);
            const unsigned nearMask = __ballot_sync(0xffffffffu, l >= mx - TH_MED);
            int idx;
            if (__popc(nearMask) == 1) {
                idx = __ffs(nearMask) - 1;
            } else {
                idx = decide_exact(zrow, bs, lane);
            }
            if (g == q) idxs[h] = idx;
        }
    }

    // ---- one-hot stores: quad-parallel STG.64 ----
#pragma unroll
    for (int h = 0; h < 2; h++) {
        const int rloc = rw0 + g + h * 8;
        const int gr   = rowBase + rloc;
        if (gr < T) {
            float* o = out + (size_t)gr * DC + 2 * a;
#pragma unroll
            for (int nt = 0; nt < 4; nt++) {
                const int ch0 = nt * 8 + 2 * a;
                float2 v;
                v.x = (ch0     == idxs[h]) ? 1.0f : 0.0f;
                v.y = (ch0 + 1 == idxs[h]) ? 1.0f : 0.0f;
                *reinterpret_cast<float2*>(o + nt * 8) = v;
            }
        }
    }
}

extern "C" void kernel_launch(void* const* d_in, const int* in_sizes, int n_in,
                              void* d_out, int out_size)
{
    const float* Z    = (const float*)d_in[0];
    const float* beta = (const float*)d_in[1];
    float* out        = (float*)d_out;

    const int T = in_sizes[0] / DZ;
    const int grid = (T + TILE - 1) / TILE;

    dec_cat_kernel<<<grid, THREADS>>>(Z, beta, out, T);
}